// round 2
// baseline (speedup 1.0000x reference)
#include <cuda_runtime.h>
#include <cuda_bf16.h>

// Problem constants
#define BATCH      4096
#define INPUT_DIM  1024
#define NUM_TREES  64
#define N_INTERNAL 63
#define N_LEAVES   64
#define LEAF_DIMS  10
#define NCOLS      (N_INTERNAL * NUM_TREES)   // 4032

// Scratch: gates[b][n][t] = sigmoid(x·W + b), 4096 * 4032 floats = 66 MB
__device__ float g_gates[BATCH * NCOLS];

// ----------------------------------------------------------------------------
// Kernel A: C = X (4096x1024) * W^T (1024x4032), fused bias + sigmoid.
// W is (63,64,1024) row-major -> row r = n*64+t of a (4032,1024) K-major matrix.
// Tiles: BM=128, BN=128, BK=16; 256 threads, 8x8 per-thread microtile.
// ----------------------------------------------------------------------------
__global__ __launch_bounds__(256, 2)
void gemm_sigmoid_kernel(const float* __restrict__ X,
                         const float* __restrict__ Wt,
                         const float* __restrict__ bias)
{
    const int BM = 128, BN = 128, BK = 16;
    __shared__ float As[BK][BM];
    __shared__ float Bs[BK][BN];

    const int tid = threadIdx.x;
    const int rowBase = blockIdx.y * BM;   // batch rows, always < 4096
    const int colBase = blockIdx.x * BN;   // gate cols, may exceed 4032 in last tile

    // cooperative load indices: 2 float4 per thread per tile
    const int innerRow = tid >> 2;          // 0..63
    const int innerCol = (tid & 3) * 4;     // 0,4,8,12

    // compute-thread indices: 16x16 grid of threads, each 8x8 outputs
    const int tx = tid & 15;
    const int ty = tid >> 4;

    float c[8][8] = {};
    float regM[8], regN[8];

    for (int kt = 0; kt < INPUT_DIM; kt += BK) {
        // --- load A tile (transposed into As[k][m]) ---
        #pragma unroll
        for (int s = 0; s < 2; ++s) {
            int r = innerRow + s * 64;
            float4 v = *reinterpret_cast<const float4*>(
                &X[(size_t)(rowBase + r) * INPUT_DIM + kt + innerCol]);
            As[innerCol + 0][r] = v.x;
            As[innerCol + 1][r] = v.y;
            As[innerCol + 2][r] = v.z;
            As[innerCol + 3][r] = v.w;
        }
        // --- load B tile (W rows = output cols), guard col < 4032 ---
        #pragma unroll
        for (int s = 0; s < 2; ++s) {
            int r = innerRow + s * 64;
            int col = colBase + r;
            float4 v = make_float4(0.f, 0.f, 0.f, 0.f);
            if (col < NCOLS)
                v = *reinterpret_cast<const float4*>(
                    &Wt[(size_t)col * INPUT_DIM + kt + innerCol]);
            Bs[innerCol + 0][r] = v.x;
            Bs[innerCol + 1][r] = v.y;
            Bs[innerCol + 2][r] = v.z;
            Bs[innerCol + 3][r] = v.w;
        }
        __syncthreads();

        #pragma unroll
        for (int kk = 0; kk < BK; ++kk) {
            #pragma unroll
            for (int i = 0; i < 8; ++i) regM[i] = As[kk][ty * 8 + i];
            #pragma unroll
            for (int j = 0; j < 8; ++j) regN[j] = Bs[kk][tx * 8 + j];
            #pragma unroll
            for (int i = 0; i < 8; ++i)
                #pragma unroll
                for (int j = 0; j < 8; ++j)
                    c[i][j] = fmaf(regM[i], regN[j], c[i][j]);
        }
        __syncthreads();
    }

    // --- epilogue: bias + sigmoid, store to g_gates ---
    #pragma unroll
    for (int i = 0; i < 8; ++i) {
        int r = rowBase + ty * 8 + i;
        #pragma unroll
        for (int j = 0; j < 8; ++j) {
            int col = colBase + tx * 8 + j;
            if (col < NCOLS) {
                float z = c[i][j] + __ldg(&bias[col]);
                float g = 1.0f / (1.0f + __expf(-z));
                g_gates[(size_t)r * NCOLS + col] = g;
            }
        }
    }
}

// ----------------------------------------------------------------------------
// Kernel B: per batch element, expand 63 gates -> 64 leaf probs per tree,
// contract against leaf_w (64,10,64), reduce over 64 trees.
// One block per batch row, 64 threads (one per tree).
// ----------------------------------------------------------------------------
__global__ __launch_bounds__(64)
void tree_kernel(const float* __restrict__ leaf_w, float* __restrict__ out)
{
    const int b = blockIdx.x;
    const int t = threadIdx.x;     // tree id, contiguous -> coalesced

    __shared__ float sg[N_INTERNAL * NUM_TREES];   // 16128 B
    __shared__ float spart[2][LEAF_DIMS];

    const float* gb = &g_gates[(size_t)b * NCOLS];
    #pragma unroll
    for (int i = t; i < NCOLS; i += NUM_TREES) sg[i] = gb[i];
    __syncthreads();

    // level-order expansion of leaf probabilities, fully in registers
    float pr[N_LEAVES];
    pr[0] = 1.0f;
    #pragma unroll
    for (int L = 0; L < 6; ++L) {
        const int num  = 1 << L;
        const int base = num - 1;
        #pragma unroll
        for (int i = num - 1; i >= 0; --i) {
            float p = pr[i];
            float g = sg[(base + i) * NUM_TREES + t];
            pr[2 * i]     = p * g;
            pr[2 * i + 1] = p * (1.0f - g);
        }
    }

    // leaf contraction: acc[d] = sum_l pr[l] * leaf_w[l][d][t]
    float acc[LEAF_DIMS];
    #pragma unroll
    for (int d = 0; d < LEAF_DIMS; ++d) acc[d] = 0.0f;
    #pragma unroll
    for (int l = 0; l < N_LEAVES; ++l) {
        float p = pr[l];
        #pragma unroll
        for (int d = 0; d < LEAF_DIMS; ++d)
            acc[d] = fmaf(p, __ldg(&leaf_w[(l * LEAF_DIMS + d) * NUM_TREES + t]), acc[d]);
    }

    // reduce over 64 trees: intra-warp shuffle, then combine the 2 warps
    #pragma unroll
    for (int d = 0; d < LEAF_DIMS; ++d) {
        float v = acc[d];
        #pragma unroll
        for (int off = 16; off > 0; off >>= 1)
            v += __shfl_xor_sync(0xffffffffu, v, off);
        acc[d] = v;
    }
    const int warp = t >> 5, lane = t & 31;
    if (lane == 0) {
        #pragma unroll
        for (int d = 0; d < LEAF_DIMS; ++d) spart[warp][d] = acc[d];
    }
    __syncthreads();
    if (t < LEAF_DIMS)
        out[(size_t)b * LEAF_DIMS + t] = spart[0][t] + spart[1][t];
}

// ----------------------------------------------------------------------------
extern "C" void kernel_launch(void* const* d_in, const int* in_sizes, int n_in,
                              void* d_out, int out_size)
{
    const float* x      = (const float*)d_in[0];   // (4096, 1024)
    const float* W      = (const float*)d_in[1];   // (63, 64, 1024)
    const float* bias   = (const float*)d_in[2];   // (63, 64)
    const float* leaf_w = (const float*)d_in[3];   // (64, 10, 64)
    float* out = (float*)d_out;                    // (4096, 10)

    dim3 ggrid((NCOLS + 127) / 128, BATCH / 128);  // (32, 32)
    gemm_sigmoid_kernel<<<ggrid, 256>>>(x, W, bias);

    tree_kernel<<<BATCH, NUM_TREES>>>(leaf_w, out);
}

// round 4
// speedup vs baseline: 2.3378x; 2.3378x over previous
#include <cuda_runtime.h>
#include <cuda_bf16.h>
#include <cstdint>

// ---------------------------------------------------------------------------
// Problem constants
// ---------------------------------------------------------------------------
#define BATCH      4096
#define INPUT_DIM  1024
#define NUM_TREES  64
#define N_INTERNAL 63
#define N_LEAVES   64
#define LEAF_DIMS  10
#define NCOLS      (N_INTERNAL * NUM_TREES)   // 4032

// GEMM tiling
#define BM       128
#define BN       128
#define BK       32                    // bf16 elems per K-chunk
#define NCHUNKS  (INPUT_DIM / BK)      // 32
#define STAGES   3
#define ROWB     80                    // 64 data bytes + 16 pad (conflict-free ldmatrix)
#define TILE_BYTES  (128 * ROWB)       // 10240
#define STAGE_BYTES (4 * TILE_BYTES)   // 40960 (Ahi, Alo, Bhi, Blo)
#define GEMM_SMEM   (STAGES * STAGE_BYTES)  // 122880

// ---------------------------------------------------------------------------
// Device scratch (no cudaMalloc allowed)
// ---------------------------------------------------------------------------
__device__ float          g_gates[(size_t)BATCH * NCOLS];      // 66 MB
__device__ __nv_bfloat16  g_xhi[(size_t)BATCH * INPUT_DIM];
__device__ __nv_bfloat16  g_xlo[(size_t)BATCH * INPUT_DIM];
__device__ __nv_bfloat16  g_whi[(size_t)NCOLS * INPUT_DIM];
__device__ __nv_bfloat16  g_wlo[(size_t)NCOLS * INPUT_DIM];

// ---------------------------------------------------------------------------
// PTX helpers (all base-sm_100-safe: cp.async, ldmatrix, mma.sync)
// ---------------------------------------------------------------------------
__device__ __forceinline__ uint32_t smem_u32(const void* p) {
    uint32_t a;
    asm("{ .reg .u64 t; cvta.to.shared.u64 t, %1; cvt.u32.u64 %0, t; }" : "=r"(a) : "l"(p));
    return a;
}

__device__ __forceinline__ void cp16(uint32_t s, const void* g, uint32_t srcBytes) {
    asm volatile("cp.async.ca.shared.global [%0], [%1], 16, %2;"
                 :: "r"(s), "l"(__cvta_generic_to_global(g)), "r"(srcBytes));
}
#define CP_COMMIT() asm volatile("cp.async.commit_group;" ::: "memory")
#define CP_WAIT1()  asm volatile("cp.async.wait_group 1;"  ::: "memory")

#define LDSM_X4(r, addr)                                                        \
    asm volatile("ldmatrix.sync.aligned.m8n8.x4.shared.b16 {%0,%1,%2,%3}, [%4];"\
                 : "=r"((r)[0]), "=r"((r)[1]), "=r"((r)[2]), "=r"((r)[3])       \
                 : "r"(addr))

__device__ __forceinline__ void mma16816(float* c, const uint32_t* a,
                                         uint32_t b0, uint32_t b1) {
    asm volatile(
        "mma.sync.aligned.m16n8k16.row.col.f32.bf16.bf16.f32 "
        "{%0,%1,%2,%3}, {%4,%5,%6,%7}, {%8,%9}, {%0,%1,%2,%3};"
        : "+f"(c[0]), "+f"(c[1]), "+f"(c[2]), "+f"(c[3])
        : "r"(a[0]), "r"(a[1]), "r"(a[2]), "r"(a[3]), "r"(b0), "r"(b1));
}

// ---------------------------------------------------------------------------
// Kernel 0: split fp32 -> (hi, lo) bf16 pair
// ---------------------------------------------------------------------------
__global__ void split_kernel(const float* __restrict__ src,
                             __nv_bfloat16* __restrict__ hi,
                             __nv_bfloat16* __restrict__ lo, int n4)
{
    int i = blockIdx.x * blockDim.x + threadIdx.x;
    if (i >= n4) return;
    float4 v = reinterpret_cast<const float4*>(src)[i];
    __nv_bfloat16 h0 = __float2bfloat16(v.x), h1 = __float2bfloat16(v.y);
    __nv_bfloat16 h2 = __float2bfloat16(v.z), h3 = __float2bfloat16(v.w);
    __nv_bfloat16 l0 = __float2bfloat16(v.x - __bfloat162float(h0));
    __nv_bfloat16 l1 = __float2bfloat16(v.y - __bfloat162float(h1));
    __nv_bfloat16 l2 = __float2bfloat16(v.z - __bfloat162float(h2));
    __nv_bfloat16 l3 = __float2bfloat16(v.w - __bfloat162float(h3));
    reinterpret_cast<__nv_bfloat162*>(hi)[2 * i]     = __nv_bfloat162(h0, h1);
    reinterpret_cast<__nv_bfloat162*>(hi)[2 * i + 1] = __nv_bfloat162(h2, h3);
    reinterpret_cast<__nv_bfloat162*>(lo)[2 * i]     = __nv_bfloat162(l0, l1);
    reinterpret_cast<__nv_bfloat162*>(lo)[2 * i + 1] = __nv_bfloat162(l2, l3);
}

// ---------------------------------------------------------------------------
// Kernel 1: bf16 mma.sync GEMM, 3-term split, fused bias+sigmoid epilogue.
// CTA 128x128, 8 warps (2 M x 4 N), warp tile 64x32, cp.async 3-stage pipe.
// ---------------------------------------------------------------------------
struct LoadCtx {
    const __nv_bfloat16 *axh, *axl, *bwh, *bwl;  // per-thread gmem row ptrs at k=0
    uint32_t wOff;      // smem offset within a tile for this thread
    uint32_t bBytes;    // 16 or 0 (N-edge zero fill)
};

__device__ __forceinline__ void issue_stage(uint32_t sb, int stage, int kt,
                                            const LoadCtx& L)
{
    const uint32_t s = sb + stage * STAGE_BYTES + L.wOff;
    // each thread: 2 x 16B per tile (ksegs ldSeg, ldSeg+1 already folded into ptrs)
    cp16(s + 0 * TILE_BYTES +  0, L.axh + kt,     16);
    cp16(s + 0 * TILE_BYTES + 16, L.axh + kt + 8, 16);
    cp16(s + 1 * TILE_BYTES +  0, L.axl + kt,     16);
    cp16(s + 1 * TILE_BYTES + 16, L.axl + kt + 8, 16);
    cp16(s + 2 * TILE_BYTES +  0, L.bwh + kt,     L.bBytes);
    cp16(s + 2 * TILE_BYTES + 16, L.bwh + kt + 8, L.bBytes);
    cp16(s + 3 * TILE_BYTES +  0, L.bwl + kt,     L.bBytes);
    cp16(s + 3 * TILE_BYTES + 16, L.bwl + kt + 8, L.bBytes);
}

__global__ void __launch_bounds__(256, 1)
gemm_mma_kernel(const float* __restrict__ bias)
{
    extern __shared__ char smem[];
    const uint32_t sb = smem_u32(smem);
    const int tid  = threadIdx.x;
    const int lane = tid & 31;
    const int wid  = tid >> 5;
    const int wm   = wid & 1;          // 0..1  (M warp)
    const int wn   = wid >> 1;         // 0..3  (N warp)

    const int rowBase = blockIdx.y * BM;
    const int colBase = blockIdx.x * BN;

    // ---- cp.async per-thread indexing: row = tid/2, ksegs = (tid&1)*2 + {0,1}
    LoadCtx L;
    {
        const int ldRow = tid >> 1;
        const int ldSeg = (tid & 1) * 2;
        const size_t aOff = (size_t)(rowBase + ldRow) * INPUT_DIM + ldSeg * 8;
        const size_t bOff = (size_t)(colBase + ldRow) * INPUT_DIM + ldSeg * 8;
        L.axh = g_xhi + aOff;  L.axl = g_xlo + aOff;
        L.bwh = g_whi + bOff;  L.bwl = g_wlo + bOff;
        L.wOff   = (uint32_t)(ldRow * ROWB + ldSeg * 16);
        L.bBytes = ((colBase + ldRow) < NCOLS) ? 16u : 0u;
    }

    // ---- ldmatrix per-lane addressing (within a tile, stage-relative)
    const int l8  = lane & 7;
    const int sel = lane >> 3;
    // A: matrices (rows0-7,k0-7) (rows8-15,k0-7) (rows0-7,k8-15) (rows8-15,k8-15)
    const uint32_t aAddr = (uint32_t)((wm * 64 + (sel & 1) * 8 + l8) * ROWB + (sel >> 1) * 16);
    // B: matrices (n0-7,k0-7) (n0-7,k8-15) (n8-15,k0-7) (n8-15,k8-15)
    const uint32_t bAddr = (uint32_t)((wn * 32 + (sel >> 1) * 8 + l8) * ROWB + (sel & 1) * 16);

    float acc[4][4][4];
    #pragma unroll
    for (int mt = 0; mt < 4; ++mt)
        #pragma unroll
        for (int nt = 0; nt < 4; ++nt)
            #pragma unroll
            for (int e = 0; e < 4; ++e) acc[mt][nt][e] = 0.0f;

    // ---- prologue: fill stages 0, 1
    issue_stage(sb, 0, 0 * BK, L);  CP_COMMIT();
    issue_stage(sb, 1, 1 * BK, L);  CP_COMMIT();

    for (int ch = 0; ch < NCHUNKS; ++ch) {
        CP_WAIT1();
        __syncthreads();

        const uint32_t st = sb + (ch % STAGES) * STAGE_BYTES;
        const uint32_t aHi = st + 0 * TILE_BYTES + aAddr;
        const uint32_t aLo = st + 1 * TILE_BYTES + aAddr;
        const uint32_t bHi = st + 2 * TILE_BYTES + bAddr;
        const uint32_t bLo = st + 3 * TILE_BYTES + bAddr;

        #pragma unroll
        for (int h = 0; h < 2; ++h) {               // two k16 steps per chunk
            uint32_t ah[4][4], al[4][4], bh[2][4], bl[2][4];
            #pragma unroll
            for (int mt = 0; mt < 4; ++mt) {
                LDSM_X4(ah[mt], aHi + mt * 16 * ROWB + h * 32);
                LDSM_X4(al[mt], aLo + mt * 16 * ROWB + h * 32);
            }
            #pragma unroll
            for (int np = 0; np < 2; ++np) {
                LDSM_X4(bh[np], bHi + np * 16 * ROWB + h * 32);
                LDSM_X4(bl[np], bLo + np * 16 * ROWB + h * 32);
            }
            #pragma unroll
            for (int mt = 0; mt < 4; ++mt)
                #pragma unroll
                for (int nt = 0; nt < 4; ++nt) {
                    const uint32_t* Bh = &bh[nt >> 1][(nt & 1) * 2];
                    const uint32_t* Bl = &bl[nt >> 1][(nt & 1) * 2];
                    mma16816(acc[mt][nt], ah[mt], Bh[0], Bh[1]);  // hi*hi
                    mma16816(acc[mt][nt], ah[mt], Bl[0], Bl[1]);  // hi*lo
                    mma16816(acc[mt][nt], al[mt], Bh[0], Bh[1]);  // lo*hi
                }
        }

        // prefetch chunk ch+2 into the stage just freed (safe: all warps passed
        // the top-of-iteration __syncthreads(), so chunk ch-1 is fully consumed)
        const int nc = ch + STAGES - 1;
        if (nc < NCHUNKS) issue_stage(sb, nc % STAGES, nc * BK, L);
        CP_COMMIT();   // commit (possibly empty) to keep group accounting uniform
    }

    // ---- epilogue: bias + sigmoid, direct from register accumulators
    const int cRow  = rowBase + wm * 64 + (lane >> 2);
    const int cCol0 = colBase + wn * 32 + (lane & 3) * 2;
    #pragma unroll
    for (int nt = 0; nt < 4; ++nt) {
        const int c = cCol0 + nt * 8;
        if (c >= NCOLS) continue;
        const float2 bv = *reinterpret_cast<const float2*>(bias + c);
        #pragma unroll
        for (int mt = 0; mt < 4; ++mt) {
            const int r0 = cRow + mt * 16;
            float2 g0, g1;
            g0.x = 1.0f / (1.0f + __expf(-(acc[mt][nt][0] + bv.x)));
            g0.y = 1.0f / (1.0f + __expf(-(acc[mt][nt][1] + bv.y)));
            g1.x = 1.0f / (1.0f + __expf(-(acc[mt][nt][2] + bv.x)));
            g1.y = 1.0f / (1.0f + __expf(-(acc[mt][nt][3] + bv.y)));
            *reinterpret_cast<float2*>(&g_gates[(size_t)r0 * NCOLS + c])       = g0;
            *reinterpret_cast<float2*>(&g_gates[(size_t)(r0 + 8) * NCOLS + c]) = g1;
        }
    }
}

// ---------------------------------------------------------------------------
// Kernel 2: tree expansion + leaf contraction (unchanged)
// ---------------------------------------------------------------------------
__global__ __launch_bounds__(64)
void tree_kernel(const float* __restrict__ leaf_w, float* __restrict__ out)
{
    const int b = blockIdx.x;
    const int t = threadIdx.x;

    __shared__ float sg[N_INTERNAL * NUM_TREES];
    __shared__ float spart[2][LEAF_DIMS];

    const float* gb = &g_gates[(size_t)b * NCOLS];
    #pragma unroll
    for (int i = t; i < NCOLS; i += NUM_TREES) sg[i] = gb[i];
    __syncthreads();

    float pr[N_LEAVES];
    pr[0] = 1.0f;
    #pragma unroll
    for (int L = 0; L < 6; ++L) {
        const int num  = 1 << L;
        const int base = num - 1;
        #pragma unroll
        for (int i = num - 1; i >= 0; --i) {
            float p = pr[i];
            float g = sg[(base + i) * NUM_TREES + t];
            pr[2 * i]     = p * g;
            pr[2 * i + 1] = p * (1.0f - g);
        }
    }

    float acc[LEAF_DIMS];
    #pragma unroll
    for (int d = 0; d < LEAF_DIMS; ++d) acc[d] = 0.0f;
    #pragma unroll
    for (int l = 0; l < N_LEAVES; ++l) {
        float p = pr[l];
        #pragma unroll
        for (int d = 0; d < LEAF_DIMS; ++d)
            acc[d] = fmaf(p, __ldg(&leaf_w[(l * LEAF_DIMS + d) * NUM_TREES + t]), acc[d]);
    }

    #pragma unroll
    for (int d = 0; d < LEAF_DIMS; ++d) {
        float v = acc[d];
        #pragma unroll
        for (int off = 16; off > 0; off >>= 1)
            v += __shfl_xor_sync(0xffffffffu, v, off);
        acc[d] = v;
    }
    const int warp = t >> 5, lane = t & 31;
    if (lane == 0) {
        #pragma unroll
        for (int d = 0; d < LEAF_DIMS; ++d) spart[warp][d] = acc[d];
    }
    __syncthreads();
    if (t < LEAF_DIMS)
        out[(size_t)b * LEAF_DIMS + t] = spart[0][t] + spart[1][t];
}

// ---------------------------------------------------------------------------
extern "C" void kernel_launch(void* const* d_in, const int* in_sizes, int n_in,
                              void* d_out, int out_size)
{
    const float* x      = (const float*)d_in[0];   // (4096, 1024)
    const float* W      = (const float*)d_in[1];   // (63, 64, 1024)
    const float* bias   = (const float*)d_in[2];   // (63, 64)
    const float* leaf_w = (const float*)d_in[3];   // (64, 10, 64)
    float* out = (float*)d_out;                    // (4096, 10)

    // idempotent, no static guards (attribute set is not a stream op)
    cudaFuncSetAttribute(gemm_mma_kernel,
                         cudaFuncAttributeMaxDynamicSharedMemorySize, GEMM_SMEM);

    __nv_bfloat16 *xhi, *xlo, *whi, *wlo;
    cudaGetSymbolAddress((void**)&xhi, g_xhi);
    cudaGetSymbolAddress((void**)&xlo, g_xlo);
    cudaGetSymbolAddress((void**)&whi, g_whi);
    cudaGetSymbolAddress((void**)&wlo, g_wlo);

    const int nx4 = BATCH * INPUT_DIM / 4;
    const int nw4 = NCOLS * INPUT_DIM / 4;
    split_kernel<<<(nx4 + 255) / 256, 256>>>(x, xhi, xlo, nx4);
    split_kernel<<<(nw4 + 255) / 256, 256>>>(W, whi, wlo, nw4);

    dim3 ggrid((NCOLS + BN - 1) / BN, BATCH / BM);   // (32, 32)
    gemm_mma_kernel<<<ggrid, 256, GEMM_SMEM>>>(bias);

    tree_kernel<<<BATCH, NUM_TREES>>>(leaf_w, out);
}

// round 5
// speedup vs baseline: 2.5431x; 1.0878x over previous
#include <cuda_runtime.h>
#include <cuda_bf16.h>
#include <cstdint>

// ---------------------------------------------------------------------------
// Problem constants
// ---------------------------------------------------------------------------
#define BATCH      4096
#define INPUT_DIM  1024
#define NUM_TREES  64
#define N_INTERNAL 63
#define N_LEAVES   64
#define LEAF_DIMS  10
#define NCOLS      (N_INTERNAL * NUM_TREES)   // 4032

// GEMM tiling
#define BM       128
#define BN       128
#define BK       32                    // bf16 elems per K-chunk
#define NCHUNKS  (INPUT_DIM / BK)      // 32
#define STAGES   2
#define ROWB     80                    // 64 data bytes + 16 pad (conflict-free ldmatrix)
#define TILE_BYTES  (128 * ROWB)       // 10240
#define STAGE_BYTES (4 * TILE_BYTES)   // 40960 (Ahi, Alo, Bhi, Blo)
#define GEMM_SMEM   (STAGES * STAGE_BYTES)  // 81920 -> 2 CTAs/SM

// ---------------------------------------------------------------------------
// Device scratch (no cudaMalloc allowed)
// ---------------------------------------------------------------------------
__device__ float          g_gates[(size_t)BATCH * NCOLS];      // 66 MB
__device__ __nv_bfloat16  g_xhi[(size_t)BATCH * INPUT_DIM];
__device__ __nv_bfloat16  g_xlo[(size_t)BATCH * INPUT_DIM];
__device__ __nv_bfloat16  g_whi[(size_t)NCOLS * INPUT_DIM];
__device__ __nv_bfloat16  g_wlo[(size_t)NCOLS * INPUT_DIM];

// ---------------------------------------------------------------------------
// PTX helpers (base-sm_100-safe: cp.async, ldmatrix, mma.sync)
// ---------------------------------------------------------------------------
__device__ __forceinline__ uint32_t smem_u32(const void* p) {
    uint32_t a;
    asm("{ .reg .u64 t; cvta.to.shared.u64 t, %1; cvt.u32.u64 %0, t; }" : "=r"(a) : "l"(p));
    return a;
}

__device__ __forceinline__ void cp16(uint32_t s, const void* g, uint32_t srcBytes) {
    asm volatile("cp.async.ca.shared.global [%0], [%1], 16, %2;"
                 :: "r"(s), "l"(__cvta_generic_to_global(g)), "r"(srcBytes));
}
#define CP_COMMIT() asm volatile("cp.async.commit_group;" ::: "memory")
#define CP_WAIT1()  asm volatile("cp.async.wait_group 1;"  ::: "memory")

#define LDSM_X4(r, addr)                                                        \
    asm volatile("ldmatrix.sync.aligned.m8n8.x4.shared.b16 {%0,%1,%2,%3}, [%4];"\
                 : "=r"((r)[0]), "=r"((r)[1]), "=r"((r)[2]), "=r"((r)[3])       \
                 : "r"(addr))

__device__ __forceinline__ void mma16816(float* c, const uint32_t* a,
                                         uint32_t b0, uint32_t b1) {
    asm volatile(
        "mma.sync.aligned.m16n8k16.row.col.f32.bf16.bf16.f32 "
        "{%0,%1,%2,%3}, {%4,%5,%6,%7}, {%8,%9}, {%0,%1,%2,%3};"
        : "+f"(c[0]), "+f"(c[1]), "+f"(c[2]), "+f"(c[3])
        : "r"(a[0]), "r"(a[1]), "r"(a[2]), "r"(a[3]), "r"(b0), "r"(b1));
}

// ---------------------------------------------------------------------------
// Kernel 0: split fp32 -> (hi, lo) bf16 pair
// ---------------------------------------------------------------------------
__global__ void split_kernel(const float* __restrict__ src,
                             __nv_bfloat16* __restrict__ hi,
                             __nv_bfloat16* __restrict__ lo, int n4)
{
    int i = blockIdx.x * blockDim.x + threadIdx.x;
    if (i >= n4) return;
    float4 v = reinterpret_cast<const float4*>(src)[i];
    __nv_bfloat16 h0 = __float2bfloat16(v.x), h1 = __float2bfloat16(v.y);
    __nv_bfloat16 h2 = __float2bfloat16(v.z), h3 = __float2bfloat16(v.w);
    __nv_bfloat16 l0 = __float2bfloat16(v.x - __bfloat162float(h0));
    __nv_bfloat16 l1 = __float2bfloat16(v.y - __bfloat162float(h1));
    __nv_bfloat16 l2 = __float2bfloat16(v.z - __bfloat162float(h2));
    __nv_bfloat16 l3 = __float2bfloat16(v.w - __bfloat162float(h3));
    reinterpret_cast<__nv_bfloat162*>(hi)[2 * i]     = __nv_bfloat162(h0, h1);
    reinterpret_cast<__nv_bfloat162*>(hi)[2 * i + 1] = __nv_bfloat162(h2, h3);
    reinterpret_cast<__nv_bfloat162*>(lo)[2 * i]     = __nv_bfloat162(l0, l1);
    reinterpret_cast<__nv_bfloat162*>(lo)[2 * i + 1] = __nv_bfloat162(l2, l3);
}

// ---------------------------------------------------------------------------
// Kernel 1: bf16 mma.sync GEMM, 3-term split, fused bias+sigmoid epilogue.
// CTA 128x128, 8 warps (2 M x 4 N), warp tile 64x32, 2-stage cp.async,
// 2 CTAs/SM for latency hiding.
// ---------------------------------------------------------------------------
struct LoadCtx {
    const __nv_bfloat16 *axh, *axl, *bwh, *bwl;
    uint32_t wOff;
    uint32_t bBytes;
};

__device__ __forceinline__ void issue_stage(uint32_t sb, int stage, int kt,
                                            const LoadCtx& L)
{
    const uint32_t s = sb + stage * STAGE_BYTES + L.wOff;
    cp16(s + 0 * TILE_BYTES +  0, L.axh + kt,     16);
    cp16(s + 0 * TILE_BYTES + 16, L.axh + kt + 8, 16);
    cp16(s + 1 * TILE_BYTES +  0, L.axl + kt,     16);
    cp16(s + 1 * TILE_BYTES + 16, L.axl + kt + 8, 16);
    cp16(s + 2 * TILE_BYTES +  0, L.bwh + kt,     L.bBytes);
    cp16(s + 2 * TILE_BYTES + 16, L.bwh + kt + 8, L.bBytes);
    cp16(s + 3 * TILE_BYTES +  0, L.bwl + kt,     L.bBytes);
    cp16(s + 3 * TILE_BYTES + 16, L.bwl + kt + 8, L.bBytes);
}

__global__ void __launch_bounds__(256, 2)
gemm_mma_kernel(const float* __restrict__ bias)
{
    extern __shared__ char smem[];
    const uint32_t sb = smem_u32(smem);
    const int tid  = threadIdx.x;
    const int lane = tid & 31;
    const int wid  = tid >> 5;
    const int wm   = wid & 1;          // M warp (0..1)
    const int wn   = wid >> 1;         // N warp (0..3)

    const int rowBase = blockIdx.y * BM;
    const int colBase = blockIdx.x * BN;

    LoadCtx L;
    {
        const int ldRow = tid >> 1;
        const int ldSeg = (tid & 1) * 2;
        const size_t aOff = (size_t)(rowBase + ldRow) * INPUT_DIM + ldSeg * 8;
        const size_t bOff = (size_t)(colBase + ldRow) * INPUT_DIM + ldSeg * 8;
        L.axh = g_xhi + aOff;  L.axl = g_xlo + aOff;
        L.bwh = g_whi + bOff;  L.bwl = g_wlo + bOff;
        L.wOff   = (uint32_t)(ldRow * ROWB + ldSeg * 16);
        L.bBytes = ((colBase + ldRow) < NCOLS) ? 16u : 0u;
    }

    const int l8  = lane & 7;
    const int sel = lane >> 3;
    const uint32_t aAddr = (uint32_t)((wm * 64 + (sel & 1) * 8 + l8) * ROWB + (sel >> 1) * 16);
    const uint32_t bAddr = (uint32_t)((wn * 32 + (sel >> 1) * 8 + l8) * ROWB + (sel & 1) * 16);

    float acc[4][4][4];
    #pragma unroll
    for (int mt = 0; mt < 4; ++mt)
        #pragma unroll
        for (int nt = 0; nt < 4; ++nt)
            #pragma unroll
            for (int e = 0; e < 4; ++e) acc[mt][nt][e] = 0.0f;

    // prologue: stage 0
    issue_stage(sb, 0, 0, L);
    CP_COMMIT();

    for (int ch = 0; ch < NCHUNKS; ++ch) {
        // prefetch next chunk into the other stage (its prior consumer finished
        // at the trailing __syncthreads() of the previous iteration)
        const int nc = ch + 1;
        if (nc < NCHUNKS) issue_stage(sb, nc & 1, nc * BK, L);
        CP_COMMIT();
        CP_WAIT1();            // current chunk's stage is resident
        __syncthreads();

        const uint32_t st = sb + (ch & 1) * STAGE_BYTES;
        const uint32_t aHi = st + 0 * TILE_BYTES + aAddr;
        const uint32_t aLo = st + 1 * TILE_BYTES + aAddr;
        const uint32_t bHi = st + 2 * TILE_BYTES + bAddr;
        const uint32_t bLo = st + 3 * TILE_BYTES + bAddr;

        #pragma unroll
        for (int h = 0; h < 2; ++h) {
            uint32_t bh[2][4], bl[2][4];
            #pragma unroll
            for (int np = 0; np < 2; ++np) {
                LDSM_X4(bh[np], bHi + np * 16 * ROWB + h * 32);
                LDSM_X4(bl[np], bLo + np * 16 * ROWB + h * 32);
            }
            #pragma unroll
            for (int mt = 0; mt < 4; ++mt) {
                uint32_t ah[4], al[4];
                LDSM_X4(ah, aHi + mt * 16 * ROWB + h * 32);
                LDSM_X4(al, aLo + mt * 16 * ROWB + h * 32);
                #pragma unroll
                for (int nt = 0; nt < 4; ++nt) {
                    const uint32_t* Bh = &bh[nt >> 1][(nt & 1) * 2];
                    const uint32_t* Bl = &bl[nt >> 1][(nt & 1) * 2];
                    mma16816(acc[mt][nt], ah, Bh[0], Bh[1]);
                    mma16816(acc[mt][nt], ah, Bl[0], Bl[1]);
                    mma16816(acc[mt][nt], al, Bh[0], Bh[1]);
                }
            }
        }
        __syncthreads();   // all warps done with this stage before it is refilled
    }

    // epilogue: bias + sigmoid from register accumulators
    const int cRow  = rowBase + wm * 64 + (lane >> 2);
    const int cCol0 = colBase + wn * 32 + (lane & 3) * 2;
    #pragma unroll
    for (int nt = 0; nt < 4; ++nt) {
        const int c = cCol0 + nt * 8;
        if (c >= NCOLS) continue;
        const float2 bv = *reinterpret_cast<const float2*>(bias + c);
        #pragma unroll
        for (int mt = 0; mt < 4; ++mt) {
            const int r0 = cRow + mt * 16;
            float2 g0, g1;
            g0.x = 1.0f / (1.0f + __expf(-(acc[mt][nt][0] + bv.x)));
            g0.y = 1.0f / (1.0f + __expf(-(acc[mt][nt][1] + bv.y)));
            g1.x = 1.0f / (1.0f + __expf(-(acc[mt][nt][2] + bv.x)));
            g1.y = 1.0f / (1.0f + __expf(-(acc[mt][nt][3] + bv.y)));
            *reinterpret_cast<float2*>(&g_gates[(size_t)r0 * NCOLS + c])       = g0;
            *reinterpret_cast<float2*>(&g_gates[(size_t)(r0 + 8) * NCOLS + c]) = g1;
        }
    }
}

// ---------------------------------------------------------------------------
// Kernel 2: tree expansion + leaf contraction.
// 256 threads = 4 batch rows x 64 trees. No smem staging of gates (per-node
// warp loads are 128B-coalesced). Last tree level fused into contraction.
// ---------------------------------------------------------------------------
__global__ __launch_bounds__(256)
void tree_kernel(const float* __restrict__ leaf_w, float* __restrict__ out)
{
    const int tid  = threadIdx.x;
    const int rg   = tid >> 6;          // row-in-block 0..3
    const int t    = tid & 63;          // tree id
    const int lane = tid & 31;
    const int wip  = (tid >> 5) & 1;    // warp-in-rowgroup

    const int b = blockIdx.x * 4 + rg;
    const float* __restrict__ gb = g_gates + (size_t)b * NCOLS;

    __shared__ float spart[4][2][LEAF_DIMS];

    // levels 0..4: expand to 32 probs in registers
    float pr[32];
    pr[0] = 1.0f;
    #pragma unroll
    for (int L = 0; L < 5; ++L) {
        const int num  = 1 << L;
        const int base = num - 1;
        #pragma unroll
        for (int i = num - 1; i >= 0; --i) {
            const float g = __ldg(gb + (base + i) * NUM_TREES + t);
            const float p = pr[i];
            pr[2 * i]     = p * g;
            pr[2 * i + 1] = p * (1.0f - g);
        }
    }

    // level 5 fused into leaf contraction:
    // acc[d] += p_i * ( w1 + g * (w0 - w1) )   with leaves (2i, 2i+1)
    float acc[LEAF_DIMS];
    #pragma unroll
    for (int d = 0; d < LEAF_DIMS; ++d) acc[d] = 0.0f;
    #pragma unroll
    for (int i = 0; i < 32; ++i) {
        const float g = __ldg(gb + (31 + i) * NUM_TREES + t);
        const float p = pr[i];
        #pragma unroll
        for (int d = 0; d < LEAF_DIMS; ++d) {
            const float w0 = __ldg(leaf_w + ((2 * i)     * LEAF_DIMS + d) * NUM_TREES + t);
            const float w1 = __ldg(leaf_w + ((2 * i + 1) * LEAF_DIMS + d) * NUM_TREES + t);
            acc[d] = fmaf(p, fmaf(g, w0 - w1, w1), acc[d]);
        }
    }

    // reduce over 64 trees: shuffle within warp, combine the 2 warps via smem
    #pragma unroll
    for (int d = 0; d < LEAF_DIMS; ++d) {
        float v = acc[d];
        #pragma unroll
        for (int off = 16; off > 0; off >>= 1)
            v += __shfl_xor_sync(0xffffffffu, v, off);
        if (lane == 0) spart[rg][wip][d] = v;
    }
    __syncthreads();
    if (tid < 4 * LEAF_DIMS) {
        const int r2 = tid / LEAF_DIMS, d = tid % LEAF_DIMS;
        out[(size_t)(blockIdx.x * 4 + r2) * LEAF_DIMS + d] =
            spart[r2][0][d] + spart[r2][1][d];
    }
}

// ---------------------------------------------------------------------------
extern "C" void kernel_launch(void* const* d_in, const int* in_sizes, int n_in,
                              void* d_out, int out_size)
{
    const float* x      = (const float*)d_in[0];   // (4096, 1024)
    const float* W      = (const float*)d_in[1];   // (63, 64, 1024)
    const float* bias   = (const float*)d_in[2];   // (63, 64)
    const float* leaf_w = (const float*)d_in[3];   // (64, 10, 64)
    float* out = (float*)d_out;                    // (4096, 10)

    cudaFuncSetAttribute(gemm_mma_kernel,
                         cudaFuncAttributeMaxDynamicSharedMemorySize, GEMM_SMEM);

    __nv_bfloat16 *xhi, *xlo, *whi, *wlo;
    cudaGetSymbolAddress((void**)&xhi, g_xhi);
    cudaGetSymbolAddress((void**)&xlo, g_xlo);
    cudaGetSymbolAddress((void**)&whi, g_whi);
    cudaGetSymbolAddress((void**)&wlo, g_wlo);

    const int nx4 = BATCH * INPUT_DIM / 4;
    const int nw4 = NCOLS * INPUT_DIM / 4;
    split_kernel<<<(nx4 + 255) / 256, 256>>>(x, xhi, xlo, nx4);
    split_kernel<<<(nw4 + 255) / 256, 256>>>(W, whi, wlo, nw4);

    dim3 ggrid((NCOLS + BN - 1) / BN, BATCH / BM);   // (32, 32)
    gemm_mma_kernel<<<ggrid, 256, GEMM_SMEM>>>(bias);

    tree_kernel<<<BATCH / 4, 256>>>(leaf_w, out);
}